// round 6
// baseline (speedup 1.0000x reference)
#include <cuda_runtime.h>
#include <cuda_fp16.h>
#include <cstdint>

#define M_DIM 8192
#define N_DIM 4096
#define K_DIM 4096
#define RANK_K 15099493u   // floor(0.9f * 16777215.0f) in fp32 semantics, frac == 0

// ---------------- device scratch (static globals: allowed) ----------------
__device__ __half   g_X16[(size_t)M_DIM * K_DIM];   // 64 MB
__device__ __half   g_W16[(size_t)N_DIM * K_DIM];   // 32 MB
__device__ unsigned g_hist1[8192];
__device__ unsigned g_hist2[262144];
__device__ unsigned g_selP;
__device__ unsigned g_selBase;
__device__ float    g_thresh;

// ---------------- PTX helpers (base ISA only) ----------------
__device__ __forceinline__ uint32_t smem_u32(const void* p) {
    uint32_t a;
    asm("{ .reg .u64 t; cvta.to.shared.u64 t, %1; cvt.u32.u64 %0, t; }" : "=r"(a) : "l"(p));
    return a;
}
__device__ __forceinline__ void cp16(uint32_t s, const void* g) {
    asm volatile("cp.async.cg.shared.global [%0], [%1], 16;" :: "r"(s), "l"(g));
}
__device__ __forceinline__ void cp_commit() { asm volatile("cp.async.commit_group;" ::: "memory"); }
__device__ __forceinline__ void cp_wait2()  { asm volatile("cp.async.wait_group 2;" ::: "memory"); }

__device__ __forceinline__ void ldsm4(uint32_t& r0, uint32_t& r1, uint32_t& r2, uint32_t& r3,
                                      uint32_t addr) {
    asm volatile("ldmatrix.sync.aligned.m8n8.x4.shared.b16 {%0,%1,%2,%3}, [%4];"
                 : "=r"(r0), "=r"(r1), "=r"(r2), "=r"(r3) : "r"(addr));
}

__device__ __forceinline__ void mma16816(float* c, const uint32_t* a, uint32_t b0, uint32_t b1) {
    asm volatile(
        "mma.sync.aligned.m16n8k16.row.col.f32.f16.f16.f32 "
        "{%0,%1,%2,%3}, {%4,%5,%6,%7}, {%8,%9}, {%0,%1,%2,%3};"
        : "+f"(c[0]), "+f"(c[1]), "+f"(c[2]), "+f"(c[3])
        : "r"(a[0]), "r"(a[1]), "r"(a[2]), "r"(a[3]), "r"(b0), "r"(b1));
}

// ---------------- selection: exact order statistic of |w| bits ----------------
__global__ void zero_kernel() {
    int i = blockIdx.x * blockDim.x + threadIdx.x;
    int st = gridDim.x * blockDim.x;
    for (int j = i; j < 8192; j += st) g_hist1[j] = 0;
    for (int j = i; j < 262144; j += st) g_hist2[j] = 0;
}

__global__ void hist1_kernel(const float4* __restrict__ w, int n4) {
    __shared__ unsigned sh[8192];
    for (int i = threadIdx.x; i < 8192; i += blockDim.x) sh[i] = 0;
    __syncthreads();
    int idx = blockIdx.x * blockDim.x + threadIdx.x;
    int stride = gridDim.x * blockDim.x;
    for (int i = idx; i < n4; i += stride) {
        float4 v = w[i];
        atomicAdd(&sh[(__float_as_uint(v.x) & 0x7FFFFFFFu) >> 18], 1u);
        atomicAdd(&sh[(__float_as_uint(v.y) & 0x7FFFFFFFu) >> 18], 1u);
        atomicAdd(&sh[(__float_as_uint(v.z) & 0x7FFFFFFFu) >> 18], 1u);
        atomicAdd(&sh[(__float_as_uint(v.w) & 0x7FFFFFFFu) >> 18], 1u);
    }
    __syncthreads();
    for (int i = threadIdx.x; i < 8192; i += blockDim.x) {
        unsigned c = sh[i];
        if (c) atomicAdd(&g_hist1[i], c);
    }
}

__global__ void scan1_kernel(unsigned rank) {
    __shared__ unsigned partial[1024];
    int t = threadIdx.x;
    unsigned v[8];
    unsigned s = 0;
#pragma unroll
    for (int i = 0; i < 8; i++) { v[i] = g_hist1[t * 8 + i]; s += v[i]; }
    partial[t] = s;
    __syncthreads();
    for (int ofs = 1; ofs < 1024; ofs <<= 1) {
        unsigned x = (t >= ofs) ? partial[t - ofs] : 0u;
        __syncthreads();
        partial[t] += x;
        __syncthreads();
    }
    unsigned base = partial[t] - s;  // exclusive prefix
    if (rank >= base && rank < partial[t]) {
        unsigned cum = base;
#pragma unroll
        for (int i = 0; i < 8; i++) {
            if (rank < cum + v[i]) { g_selP = (unsigned)(t * 8 + i); g_selBase = cum; break; }
            cum += v[i];
        }
    }
}

__global__ void hist2_kernel(const float4* __restrict__ w, int n4) {
    unsigned P = g_selP;
    int idx = blockIdx.x * blockDim.x + threadIdx.x;
    int stride = gridDim.x * blockDim.x;
    for (int i = idx; i < n4; i += stride) {
        float4 v = w[i];
        unsigned b;
        b = __float_as_uint(v.x) & 0x7FFFFFFFu; if ((b >> 18) == P) atomicAdd(&g_hist2[b & 0x3FFFFu], 1u);
        b = __float_as_uint(v.y) & 0x7FFFFFFFu; if ((b >> 18) == P) atomicAdd(&g_hist2[b & 0x3FFFFu], 1u);
        b = __float_as_uint(v.z) & 0x7FFFFFFFu; if ((b >> 18) == P) atomicAdd(&g_hist2[b & 0x3FFFFu], 1u);
        b = __float_as_uint(v.w) & 0x7FFFFFFFu; if ((b >> 18) == P) atomicAdd(&g_hist2[b & 0x3FFFFu], 1u);
    }
}

__global__ void scan2_kernel(unsigned rank) {
    __shared__ unsigned partial[1024];
    int t = threadIdx.x;
    unsigned s = 0;
    for (int i = 0; i < 256; i++) s += g_hist2[t * 256 + i];
    partial[t] = s;
    __syncthreads();
    for (int ofs = 1; ofs < 1024; ofs <<= 1) {
        unsigned x = (t >= ofs) ? partial[t - ofs] : 0u;
        __syncthreads();
        partial[t] += x;
        __syncthreads();
    }
    unsigned base = partial[t] - s;
    unsigned rl = rank - g_selBase;
    if (rl >= base && rl < partial[t]) {
        unsigned cum = base;
        for (int i = 0; i < 256; i++) {
            unsigned c = g_hist2[t * 256 + i];
            if (rl < cum + c) {
                g_thresh = __uint_as_float((g_selP << 18) | (unsigned)(t * 256 + i));
                break;
            }
            cum += c;
        }
    }
}

// ---------------- fp16 conversion ----------------
__global__ void conv_x_kernel(const float4* __restrict__ x, int n4) {
    int idx = blockIdx.x * blockDim.x + threadIdx.x;
    int stride = gridDim.x * blockDim.x;
    uint2* out = reinterpret_cast<uint2*>(g_X16);
    for (int i = idx; i < n4; i += stride) {
        float4 v = x[i];
        __half2 h0 = __floats2half2_rn(v.x, v.y);
        __half2 h1 = __floats2half2_rn(v.z, v.w);
        uint2 o;
        o.x = *reinterpret_cast<unsigned*>(&h0);
        o.y = *reinterpret_cast<unsigned*>(&h1);
        out[i] = o;
    }
}

__global__ void conv_w_kernel(const float4* __restrict__ w, int n4) {
    float t = g_thresh;
    int idx = blockIdx.x * blockDim.x + threadIdx.x;
    int stride = gridDim.x * blockDim.x;
    uint2* out = reinterpret_cast<uint2*>(g_W16);
    for (int i = idx; i < n4; i += stride) {
        float4 v = w[i];
        float a0 = (fabsf(v.x) >= t) ? v.x : 0.0f;
        float a1 = (fabsf(v.y) >= t) ? v.y : 0.0f;
        float a2 = (fabsf(v.z) >= t) ? v.z : 0.0f;
        float a3 = (fabsf(v.w) >= t) ? v.w : 0.0f;
        __half2 h0 = __floats2half2_rn(a0, a1);
        __half2 h1 = __floats2half2_rn(a2, a3);
        uint2 o;
        o.x = *reinterpret_cast<unsigned*>(&h0);
        o.y = *reinterpret_cast<unsigned*>(&h1);
        out[i] = o;
    }
}

// ---------------- GEMM: 256x128 CTA tile, 64x64 warp tiles, 3-stage cp.async ----------------
#define BM 256
#define BN 128
#define BKH 64                      // K halves per stage (128 B per row -> SW128)
#define NK (K_DIM / BKH)            // 64
#define STG 3
#define A_BYTES (BM * 128)          // 32768
#define B_BYTES (BN * 128)          // 16384
#define STAGE_B (A_BYTES + B_BYTES) // 49152
#define SMEM_GEMM (STG * STAGE_B)   // 147456

__device__ __forceinline__ void load_stage(uint32_t st, int m0, int n0, int kidx, int tid) {
    const __half* Xp = g_X16 + (size_t)m0 * K_DIM + (size_t)kidx * BKH;
    const __half* Wp = g_W16 + (size_t)n0 * K_DIM + (size_t)kidx * BKH;
#pragma unroll
    for (int i = 0; i < 8; i++) {
        int c = tid + i * 256;           // 0..2047 (256 rows x 8 chunks)
        int row = c >> 3, ci = c & 7;
        cp16(st + row * 128 + ((ci ^ (row & 7)) << 4), Xp + (size_t)row * K_DIM + ci * 8);
    }
#pragma unroll
    for (int i = 0; i < 4; i++) {
        int c = tid + i * 256;           // 0..1023 (128 rows x 8 chunks)
        int row = c >> 3, ci = c & 7;
        cp16(st + A_BYTES + row * 128 + ((ci ^ (row & 7)) << 4), Wp + (size_t)row * K_DIM + ci * 8);
    }
}

__global__ void __launch_bounds__(256, 1) gemm_kernel(const float* __restrict__ bias,
                                                      float* __restrict__ out) {
    extern __shared__ char smraw[];
    const uint32_t sbase = smem_u32(smraw);
    const int tid = threadIdx.x;
    const int wid = tid >> 5;
    const int lane = tid & 31;
    const int warp_m = wid >> 1;     // 0..3 (64 rows each)
    const int warp_n = wid & 1;      // 0..1 (64 cols each)
    const int m0 = blockIdx.y * BM;
    const int n0 = blockIdx.x * BN;

    float acc[4][8][4];
#pragma unroll
    for (int i = 0; i < 4; i++)
#pragma unroll
        for (int j = 0; j < 8; j++)
#pragma unroll
            for (int k = 0; k < 4; k++) acc[i][j][k] = 0.0f;

    // ldmatrix lane geometry
    const int g  = lane >> 3;             // 0..3
    const int lr = lane & 7;
    const int r16 = ((g & 1) << 3) + lr;  // row within a 16-row tile
    const int kg  = g >> 1;               // 16B chunk parity within k16

    // prologue
    load_stage(sbase + 0 * STAGE_B, m0, n0, 0, tid); cp_commit();
    load_stage(sbase + 1 * STAGE_B, m0, n0, 1, tid); cp_commit();

    for (int ki = 0; ki < NK; ki++) {
        if (ki + 2 < NK) load_stage(sbase + ((ki + 2) % STG) * STAGE_B, m0, n0, ki + 2, tid);
        cp_commit();
        cp_wait2();          // stage ki resident
        __syncthreads();

        const uint32_t sA = sbase + (uint32_t)(ki % STG) * STAGE_B;
        const uint32_t sB = sA + A_BYTES;

#pragma unroll
        for (int ks = 0; ks < 4; ks++) {            // 4 x k16 per stage
            const int chunk = ks * 2 + kg;           // 16B chunk index 0..7
            uint32_t a[4][4], b[4][4];
#pragma unroll
            for (int mt = 0; mt < 4; mt++) {
                int row = warp_m * 64 + mt * 16 + r16;
                uint32_t ad = sA + row * 128 + ((chunk ^ (row & 7)) << 4);
                ldsm4(a[mt][0], a[mt][1], a[mt][2], a[mt][3], ad);
            }
#pragma unroll
            for (int bt = 0; bt < 4; bt++) {
                int row = warp_n * 64 + bt * 16 + r16;
                uint32_t ad = sB + row * 128 + ((chunk ^ (row & 7)) << 4);
                ldsm4(b[bt][0], b[bt][1], b[bt][2], b[bt][3], ad);
            }
#pragma unroll
            for (int mt = 0; mt < 4; mt++)
#pragma unroll
                for (int nt = 0; nt < 8; nt++) {
                    int bt = nt >> 1, od = nt & 1;
                    mma16816(acc[mt][nt], a[mt], b[bt][od], b[bt][2 + od]);
                }
        }
        __syncthreads();    // protect stage (ki%STG) before it is reloaded
    }

    // epilogue
    const int qr = lane >> 2, qc = lane & 3;
#pragma unroll
    for (int nt = 0; nt < 8; nt++) {
        int col = n0 + warp_n * 64 + nt * 8 + qc * 2;
        float2 bb = *reinterpret_cast<const float2*>(bias + col);
#pragma unroll
        for (int mt = 0; mt < 4; mt++) {
            int r0 = m0 + warp_m * 64 + mt * 16 + qr;
            float2 v0, v1;
            v0.x = acc[mt][nt][0] + bb.x;  v0.y = acc[mt][nt][1] + bb.y;
            v1.x = acc[mt][nt][2] + bb.x;  v1.y = acc[mt][nt][3] + bb.y;
            *reinterpret_cast<float2*>(out + (size_t)r0 * N_DIM + col) = v0;
            *reinterpret_cast<float2*>(out + (size_t)(r0 + 8) * N_DIM + col) = v1;
        }
    }
}

// ---------------- launch ----------------
extern "C" void kernel_launch(void* const* d_in, const int* in_sizes, int n_in,
                              void* d_out, int out_size) {
    (void)in_sizes; (void)n_in; (void)out_size;
    const float4* x4 = reinterpret_cast<const float4*>(d_in[0]);
    const float4* w4 = reinterpret_cast<const float4*>(d_in[1]);
    const float*  bias = reinterpret_cast<const float*>(d_in[2]);
    float* out = reinterpret_cast<float*>(d_out);

    const int NW4 = (N_DIM * K_DIM) / 4;   // 4194304
    const int NX4 = (M_DIM * K_DIM) / 4;   // 8388608

    cudaFuncSetAttribute(gemm_kernel, cudaFuncAttributeMaxDynamicSharedMemorySize, SMEM_GEMM);

    zero_kernel<<<512, 256>>>();
    hist1_kernel<<<1184, 256>>>(w4, NW4);
    scan1_kernel<<<1, 1024>>>(RANK_K);
    hist2_kernel<<<1184, 256>>>(w4, NW4);
    scan2_kernel<<<1, 1024>>>(RANK_K);
    conv_x_kernel<<<1184, 256>>>(x4, NX4);
    conv_w_kernel<<<1184, 256>>>(w4, NW4);
    gemm_kernel<<<dim3(N_DIM / BN, M_DIM / BM), 256, SMEM_GEMM>>>(bias, out);
}

// round 7
// speedup vs baseline: 1.0674x; 1.0674x over previous
#include <cuda_runtime.h>
#include <cuda_fp16.h>
#include <cstdint>

#define M_DIM 8192
#define N_DIM 4096
#define K_DIM 4096
#define RANK_K 15099493u   // floor(0.9f * 16777215.0f) in fp32 semantics, frac == 0

// ---------------- device scratch (static globals: allowed) ----------------
__device__ __half   g_X16[(size_t)M_DIM * K_DIM];   // 64 MB
__device__ __half   g_W16[(size_t)N_DIM * K_DIM];   // 32 MB
__device__ unsigned g_hist1[8192];
__device__ unsigned g_hist2[262144];
__device__ unsigned g_selP;
__device__ unsigned g_selBase;
__device__ float    g_thresh;

// ---------------- PTX helpers (base ISA only) ----------------
__device__ __forceinline__ uint32_t smem_u32(const void* p) {
    uint32_t a;
    asm("{ .reg .u64 t; cvta.to.shared.u64 t, %1; cvt.u32.u64 %0, t; }" : "=r"(a) : "l"(p));
    return a;
}
__device__ __forceinline__ void cp16(uint32_t s, const void* g) {
    asm volatile("cp.async.cg.shared.global [%0], [%1], 16;" :: "r"(s), "l"(g));
}
__device__ __forceinline__ void cp_commit() { asm volatile("cp.async.commit_group;" ::: "memory"); }
__device__ __forceinline__ void cp_wait2()  { asm volatile("cp.async.wait_group 2;" ::: "memory"); }

__device__ __forceinline__ void ldsm4(uint32_t& r0, uint32_t& r1, uint32_t& r2, uint32_t& r3,
                                      uint32_t addr) {
    asm volatile("ldmatrix.sync.aligned.m8n8.x4.shared.b16 {%0,%1,%2,%3}, [%4];"
                 : "=r"(r0), "=r"(r1), "=r"(r2), "=r"(r3) : "r"(addr));
}

__device__ __forceinline__ void mma16816(float* c, const uint32_t* a, uint32_t b0, uint32_t b1) {
    asm volatile(
        "mma.sync.aligned.m16n8k16.row.col.f32.f16.f16.f32 "
        "{%0,%1,%2,%3}, {%4,%5,%6,%7}, {%8,%9}, {%0,%1,%2,%3};"
        : "+f"(c[0]), "+f"(c[1]), "+f"(c[2]), "+f"(c[3])
        : "r"(a[0]), "r"(a[1]), "r"(a[2]), "r"(a[3]), "r"(b0), "r"(b1));
}

// ---------------- selection: exact order statistic of |w| bits ----------------
__global__ void zero_kernel() {
    int i = blockIdx.x * blockDim.x + threadIdx.x;
    int st = gridDim.x * blockDim.x;
    for (int j = i; j < 8192; j += st) g_hist1[j] = 0;
    for (int j = i; j < 262144; j += st) g_hist2[j] = 0;
}

__global__ void hist1_kernel(const float4* __restrict__ w, int n4) {
    __shared__ unsigned sh[8192];
    for (int i = threadIdx.x; i < 8192; i += blockDim.x) sh[i] = 0;
    __syncthreads();
    int idx = blockIdx.x * blockDim.x + threadIdx.x;
    int stride = gridDim.x * blockDim.x;
    for (int i = idx; i < n4; i += stride) {
        float4 v = w[i];
        atomicAdd(&sh[(__float_as_uint(v.x) & 0x7FFFFFFFu) >> 18], 1u);
        atomicAdd(&sh[(__float_as_uint(v.y) & 0x7FFFFFFFu) >> 18], 1u);
        atomicAdd(&sh[(__float_as_uint(v.z) & 0x7FFFFFFFu) >> 18], 1u);
        atomicAdd(&sh[(__float_as_uint(v.w) & 0x7FFFFFFFu) >> 18], 1u);
    }
    __syncthreads();
    for (int i = threadIdx.x; i < 8192; i += blockDim.x) {
        unsigned c = sh[i];
        if (c) atomicAdd(&g_hist1[i], c);
    }
}

__global__ void scan1_kernel(unsigned rank) {
    __shared__ unsigned partial[1024];
    int t = threadIdx.x;
    unsigned v[8];
    unsigned s = 0;
#pragma unroll
    for (int i = 0; i < 8; i++) { v[i] = g_hist1[t * 8 + i]; s += v[i]; }
    partial[t] = s;
    __syncthreads();
    for (int ofs = 1; ofs < 1024; ofs <<= 1) {
        unsigned x = (t >= ofs) ? partial[t - ofs] : 0u;
        __syncthreads();
        partial[t] += x;
        __syncthreads();
    }
    unsigned base = partial[t] - s;  // exclusive prefix
    if (rank >= base && rank < partial[t]) {
        unsigned cum = base;
#pragma unroll
        for (int i = 0; i < 8; i++) {
            if (rank < cum + v[i]) { g_selP = (unsigned)(t * 8 + i); g_selBase = cum; break; }
            cum += v[i];
        }
    }
}

__global__ void hist2_kernel(const float4* __restrict__ w, int n4) {
    unsigned P = g_selP;
    int idx = blockIdx.x * blockDim.x + threadIdx.x;
    int stride = gridDim.x * blockDim.x;
    for (int i = idx; i < n4; i += stride) {
        float4 v = w[i];
        unsigned b;
        b = __float_as_uint(v.x) & 0x7FFFFFFFu; if ((b >> 18) == P) atomicAdd(&g_hist2[b & 0x3FFFFu], 1u);
        b = __float_as_uint(v.y) & 0x7FFFFFFFu; if ((b >> 18) == P) atomicAdd(&g_hist2[b & 0x3FFFFu], 1u);
        b = __float_as_uint(v.z) & 0x7FFFFFFFu; if ((b >> 18) == P) atomicAdd(&g_hist2[b & 0x3FFFFu], 1u);
        b = __float_as_uint(v.w) & 0x7FFFFFFFu; if ((b >> 18) == P) atomicAdd(&g_hist2[b & 0x3FFFFu], 1u);
    }
}

__global__ void scan2_kernel(unsigned rank) {
    __shared__ unsigned partial[1024];
    int t = threadIdx.x;
    unsigned s = 0;
    for (int i = 0; i < 256; i++) s += g_hist2[t * 256 + i];
    partial[t] = s;
    __syncthreads();
    for (int ofs = 1; ofs < 1024; ofs <<= 1) {
        unsigned x = (t >= ofs) ? partial[t - ofs] : 0u;
        __syncthreads();
        partial[t] += x;
        __syncthreads();
    }
    unsigned base = partial[t] - s;
    unsigned rl = rank - g_selBase;
    if (rl >= base && rl < partial[t]) {
        unsigned cum = base;
        for (int i = 0; i < 256; i++) {
            unsigned c = g_hist2[t * 256 + i];
            if (rl < cum + c) {
                g_thresh = __uint_as_float((g_selP << 18) | (unsigned)(t * 256 + i));
                break;
            }
            cum += c;
        }
    }
}

// ---------------- fp16 conversion ----------------
__global__ void conv_x_kernel(const float4* __restrict__ x, int n4) {
    int idx = blockIdx.x * blockDim.x + threadIdx.x;
    int stride = gridDim.x * blockDim.x;
    uint2* out = reinterpret_cast<uint2*>(g_X16);
    for (int i = idx; i < n4; i += stride) {
        float4 v = x[i];
        __half2 h0 = __floats2half2_rn(v.x, v.y);
        __half2 h1 = __floats2half2_rn(v.z, v.w);
        uint2 o;
        o.x = *reinterpret_cast<unsigned*>(&h0);
        o.y = *reinterpret_cast<unsigned*>(&h1);
        out[i] = o;
    }
}

__global__ void conv_w_kernel(const float4* __restrict__ w, int n4) {
    float t = g_thresh;
    int idx = blockIdx.x * blockDim.x + threadIdx.x;
    int stride = gridDim.x * blockDim.x;
    uint2* out = reinterpret_cast<uint2*>(g_W16);
    for (int i = idx; i < n4; i += stride) {
        float4 v = w[i];
        float a0 = (fabsf(v.x) >= t) ? v.x : 0.0f;
        float a1 = (fabsf(v.y) >= t) ? v.y : 0.0f;
        float a2 = (fabsf(v.z) >= t) ? v.z : 0.0f;
        float a3 = (fabsf(v.w) >= t) ? v.w : 0.0f;
        __half2 h0 = __floats2half2_rn(a0, a1);
        __half2 h1 = __floats2half2_rn(a2, a3);
        uint2 o;
        o.x = *reinterpret_cast<unsigned*>(&h0);
        o.y = *reinterpret_cast<unsigned*>(&h1);
        out[i] = o;
    }
}

// ---- GEMM: 128x128 CTA tile, 4 warps (64x64 warp tiles), 3-stage cp.async, occ=2 ----
#define BM 128
#define BN 128
#define BKH 64                      // K halves per stage (128 B rows -> SW128)
#define NK (K_DIM / BKH)            // 64
#define STG 3
#define OP_BYTES (BM * 128)         // 16384
#define STAGE_B (2 * OP_BYTES)      // 32768
#define SMEM_GEMM (STG * STAGE_B)   // 98304 per CTA (x2 CTAs = 192K < 228K)
#define NTHR 128

__device__ __forceinline__ void load_stage(uint32_t st, int m0, int n0, int kidx, int tid) {
    const __half* Xp = g_X16 + (size_t)m0 * K_DIM + (size_t)kidx * BKH;
    const __half* Wp = g_W16 + (size_t)n0 * K_DIM + (size_t)kidx * BKH;
#pragma unroll
    for (int i = 0; i < 8; i++) {
        int c = tid + i * NTHR;          // 0..1023 (128 rows x 8 chunks)
        int row = c >> 3, ci = c & 7;
        cp16(st + row * 128 + ((ci ^ (row & 7)) << 4), Xp + (size_t)row * K_DIM + ci * 8);
    }
#pragma unroll
    for (int i = 0; i < 8; i++) {
        int c = tid + i * NTHR;
        int row = c >> 3, ci = c & 7;
        cp16(st + OP_BYTES + row * 128 + ((ci ^ (row & 7)) << 4), Wp + (size_t)row * K_DIM + ci * 8);
    }
}

__global__ void __launch_bounds__(NTHR, 2) gemm_kernel(const float* __restrict__ bias,
                                                       float* __restrict__ out) {
    extern __shared__ char smraw[];
    const uint32_t sbase = smem_u32(smraw);
    const int tid = threadIdx.x;
    const int wid = tid >> 5;
    const int lane = tid & 31;
    const int warp_m = wid >> 1;     // 0..1 (64 rows each)
    const int warp_n = wid & 1;      // 0..1 (64 cols each)
    const int m0 = blockIdx.y * BM;
    const int n0 = blockIdx.x * BN;

    float acc[4][8][4];
#pragma unroll
    for (int i = 0; i < 4; i++)
#pragma unroll
        for (int j = 0; j < 8; j++)
#pragma unroll
            for (int k = 0; k < 4; k++) acc[i][j][k] = 0.0f;

    // ldmatrix lane geometry
    const int g  = lane >> 3;             // 0..3
    const int lr = lane & 7;
    const int r16 = ((g & 1) << 3) + lr;  // row within a 16-row tile
    const int kg  = g >> 1;               // 16B chunk parity within k16

    // prologue
    load_stage(sbase + 0 * STAGE_B, m0, n0, 0, tid); cp_commit();
    load_stage(sbase + 1 * STAGE_B, m0, n0, 1, tid); cp_commit();

    for (int ki = 0; ki < NK; ki++) {
        if (ki + 2 < NK) load_stage(sbase + ((ki + 2) % STG) * STAGE_B, m0, n0, ki + 2, tid);
        cp_commit();
        cp_wait2();          // stage ki resident
        __syncthreads();

        const uint32_t sA = sbase + (uint32_t)(ki % STG) * STAGE_B;
        const uint32_t sB = sA + OP_BYTES;

#pragma unroll
        for (int ks = 0; ks < 4; ks++) {            // 4 x k16 per stage
            const int chunk = ks * 2 + kg;           // 16B chunk index 0..7
            uint32_t a[4][4], b[4][4];
#pragma unroll
            for (int mt = 0; mt < 4; mt++) {
                int row = warp_m * 64 + mt * 16 + r16;
                uint32_t ad = sA + row * 128 + ((chunk ^ (row & 7)) << 4);
                ldsm4(a[mt][0], a[mt][1], a[mt][2], a[mt][3], ad);
            }
#pragma unroll
            for (int bt = 0; bt < 4; bt++) {
                int row = warp_n * 64 + bt * 16 + r16;
                uint32_t ad = sB + row * 128 + ((chunk ^ (row & 7)) << 4);
                ldsm4(b[bt][0], b[bt][1], b[bt][2], b[bt][3], ad);
            }
#pragma unroll
            for (int mt = 0; mt < 4; mt++)
#pragma unroll
                for (int nt = 0; nt < 8; nt++) {
                    int bt = nt >> 1, od = nt & 1;
                    mma16816(acc[mt][nt], a[mt], b[bt][od], b[bt][2 + od]);
                }
        }
        __syncthreads();    // protect stage (ki%STG) before it is reloaded
    }

    // epilogue
    const int qr = lane >> 2, qc = lane & 3;
#pragma unroll
    for (int nt = 0; nt < 8; nt++) {
        int col = n0 + warp_n * 64 + nt * 8 + qc * 2;
        float2 bb = *reinterpret_cast<const float2*>(bias + col);
#pragma unroll
        for (int mt = 0; mt < 4; mt++) {
            int r0 = m0 + warp_m * 64 + mt * 16 + qr;
            float2 v0, v1;
            v0.x = acc[mt][nt][0] + bb.x;  v0.y = acc[mt][nt][1] + bb.y;
            v1.x = acc[mt][nt][2] + bb.x;  v1.y = acc[mt][nt][3] + bb.y;
            *reinterpret_cast<float2*>(out + (size_t)r0 * N_DIM + col) = v0;
            *reinterpret_cast<float2*>(out + (size_t)(r0 + 8) * N_DIM + col) = v1;
        }
    }
}

// ---------------- launch ----------------
extern "C" void kernel_launch(void* const* d_in, const int* in_sizes, int n_in,
                              void* d_out, int out_size) {
    (void)in_sizes; (void)n_in; (void)out_size;
    const float4* x4 = reinterpret_cast<const float4*>(d_in[0]);
    const float4* w4 = reinterpret_cast<const float4*>(d_in[1]);
    const float*  bias = reinterpret_cast<const float*>(d_in[2]);
    float* out = reinterpret_cast<float*>(d_out);

    const int NW4 = (N_DIM * K_DIM) / 4;   // 4194304
    const int NX4 = (M_DIM * K_DIM) / 4;   // 8388608

    cudaFuncSetAttribute(gemm_kernel, cudaFuncAttributeMaxDynamicSharedMemorySize, SMEM_GEMM);

    zero_kernel<<<512, 256>>>();
    hist1_kernel<<<1184, 256>>>(w4, NW4);
    scan1_kernel<<<1, 1024>>>(RANK_K);
    hist2_kernel<<<1184, 256>>>(w4, NW4);
    scan2_kernel<<<1, 1024>>>(RANK_K);
    conv_x_kernel<<<1184, 256>>>(x4, NX4);
    conv_w_kernel<<<1184, 256>>>(w4, NW4);
    gemm_kernel<<<dim3(N_DIM / BN, M_DIM / BM), NTHR, SMEM_GEMM>>>(bias, out);
}

// round 8
// speedup vs baseline: 1.0735x; 1.0057x over previous
#include <cuda_runtime.h>
#include <cuda_fp16.h>
#include <cstdint>

#define M_DIM 8192
#define N_DIM 4096
#define K_DIM 4096
#define RANK_K 15099493u   // floor(0.9f * 16777215.0f) in fp32 semantics, frac == 0

// ---------------- device scratch (static globals: allowed) ----------------
__device__ __half   g_X16[(size_t)M_DIM * K_DIM];   // 64 MB
__device__ __half   g_W16[(size_t)N_DIM * K_DIM];   // 32 MB
__device__ unsigned g_hist1[8192];
__device__ unsigned g_hist2[262144];
__device__ unsigned g_selP;
__device__ unsigned g_selBase;
__device__ float    g_thresh;

// ---------------- PTX helpers (base ISA only) ----------------
__device__ __forceinline__ uint32_t smem_u32(const void* p) {
    uint32_t a;
    asm("{ .reg .u64 t; cvta.to.shared.u64 t, %1; cvt.u32.u64 %0, t; }" : "=r"(a) : "l"(p));
    return a;
}
__device__ __forceinline__ void cp16(uint32_t s, const void* g) {
    asm volatile("cp.async.cg.shared.global [%0], [%1], 16;" :: "r"(s), "l"(g));
}
__device__ __forceinline__ void cp_commit() { asm volatile("cp.async.commit_group;" ::: "memory"); }
__device__ __forceinline__ void cp_wait2()  { asm volatile("cp.async.wait_group 2;" ::: "memory"); }

__device__ __forceinline__ void ldsm4(uint32_t& r0, uint32_t& r1, uint32_t& r2, uint32_t& r3,
                                      uint32_t addr) {
    asm volatile("ldmatrix.sync.aligned.m8n8.x4.shared.b16 {%0,%1,%2,%3}, [%4];"
                 : "=r"(r0), "=r"(r1), "=r"(r2), "=r"(r3) : "r"(addr));
}

__device__ __forceinline__ void mma16816(float* c, const uint32_t* a, uint32_t b0, uint32_t b1) {
    asm volatile(
        "mma.sync.aligned.m16n8k16.row.col.f32.f16.f16.f32 "
        "{%0,%1,%2,%3}, {%4,%5,%6,%7}, {%8,%9}, {%0,%1,%2,%3};"
        : "+f"(c[0]), "+f"(c[1]), "+f"(c[2]), "+f"(c[3])
        : "r"(a[0]), "r"(a[1]), "r"(a[2]), "r"(a[3]), "r"(b0), "r"(b1));
}

// ---------------- selection: exact order statistic of |w| bits ----------------
__global__ void zero_kernel() {
    int i = blockIdx.x * blockDim.x + threadIdx.x;
    int st = gridDim.x * blockDim.x;
    for (int j = i; j < 8192; j += st) g_hist1[j] = 0;
    for (int j = i; j < 262144; j += st) g_hist2[j] = 0;
}

__global__ void hist1_kernel(const float4* __restrict__ w, int n4) {
    __shared__ unsigned sh[8192];
    for (int i = threadIdx.x; i < 8192; i += blockDim.x) sh[i] = 0;
    __syncthreads();
    int idx = blockIdx.x * blockDim.x + threadIdx.x;
    int stride = gridDim.x * blockDim.x;
    for (int i = idx; i < n4; i += stride) {
        float4 v = w[i];
        atomicAdd(&sh[(__float_as_uint(v.x) & 0x7FFFFFFFu) >> 18], 1u);
        atomicAdd(&sh[(__float_as_uint(v.y) & 0x7FFFFFFFu) >> 18], 1u);
        atomicAdd(&sh[(__float_as_uint(v.z) & 0x7FFFFFFFu) >> 18], 1u);
        atomicAdd(&sh[(__float_as_uint(v.w) & 0x7FFFFFFFu) >> 18], 1u);
    }
    __syncthreads();
    for (int i = threadIdx.x; i < 8192; i += blockDim.x) {
        unsigned c = sh[i];
        if (c) atomicAdd(&g_hist1[i], c);
    }
}

__global__ void scan1_kernel(unsigned rank) {
    __shared__ unsigned partial[1024];
    int t = threadIdx.x;
    unsigned v[8];
    unsigned s = 0;
#pragma unroll
    for (int i = 0; i < 8; i++) { v[i] = g_hist1[t * 8 + i]; s += v[i]; }
    partial[t] = s;
    __syncthreads();
    for (int ofs = 1; ofs < 1024; ofs <<= 1) {
        unsigned x = (t >= ofs) ? partial[t - ofs] : 0u;
        __syncthreads();
        partial[t] += x;
        __syncthreads();
    }
    unsigned base = partial[t] - s;  // exclusive prefix
    if (rank >= base && rank < partial[t]) {
        unsigned cum = base;
#pragma unroll
        for (int i = 0; i < 8; i++) {
            if (rank < cum + v[i]) { g_selP = (unsigned)(t * 8 + i); g_selBase = cum; break; }
            cum += v[i];
        }
    }
}

__global__ void hist2_kernel(const float4* __restrict__ w, int n4) {
    unsigned P = g_selP;
    int idx = blockIdx.x * blockDim.x + threadIdx.x;
    int stride = gridDim.x * blockDim.x;
    for (int i = idx; i < n4; i += stride) {
        float4 v = w[i];
        unsigned b;
        b = __float_as_uint(v.x) & 0x7FFFFFFFu; if ((b >> 18) == P) atomicAdd(&g_hist2[b & 0x3FFFFu], 1u);
        b = __float_as_uint(v.y) & 0x7FFFFFFFu; if ((b >> 18) == P) atomicAdd(&g_hist2[b & 0x3FFFFu], 1u);
        b = __float_as_uint(v.z) & 0x7FFFFFFFu; if ((b >> 18) == P) atomicAdd(&g_hist2[b & 0x3FFFFu], 1u);
        b = __float_as_uint(v.w) & 0x7FFFFFFFu; if ((b >> 18) == P) atomicAdd(&g_hist2[b & 0x3FFFFu], 1u);
    }
}

__global__ void scan2_kernel(unsigned rank) {
    __shared__ unsigned partial[1024];
    int t = threadIdx.x;
    unsigned s = 0;
    for (int i = 0; i < 256; i++) s += g_hist2[t * 256 + i];
    partial[t] = s;
    __syncthreads();
    for (int ofs = 1; ofs < 1024; ofs <<= 1) {
        unsigned x = (t >= ofs) ? partial[t - ofs] : 0u;
        __syncthreads();
        partial[t] += x;
        __syncthreads();
    }
    unsigned base = partial[t] - s;
    unsigned rl = rank - g_selBase;
    if (rl >= base && rl < partial[t]) {
        unsigned cum = base;
        for (int i = 0; i < 256; i++) {
            unsigned c = g_hist2[t * 256 + i];
            if (rl < cum + c) {
                g_thresh = __uint_as_float((g_selP << 18) | (unsigned)(t * 256 + i));
                break;
            }
            cum += c;
        }
    }
}

// ---------------- fp16 conversion ----------------
__global__ void conv_x_kernel(const float4* __restrict__ x, int n4) {
    int idx = blockIdx.x * blockDim.x + threadIdx.x;
    int stride = gridDim.x * blockDim.x;
    uint2* out = reinterpret_cast<uint2*>(g_X16);
    for (int i = idx; i < n4; i += stride) {
        float4 v = x[i];
        __half2 h0 = __floats2half2_rn(v.x, v.y);
        __half2 h1 = __floats2half2_rn(v.z, v.w);
        uint2 o;
        o.x = *reinterpret_cast<unsigned*>(&h0);
        o.y = *reinterpret_cast<unsigned*>(&h1);
        out[i] = o;
    }
}

__global__ void conv_w_kernel(const float4* __restrict__ w, int n4) {
    float t = g_thresh;
    int idx = blockIdx.x * blockDim.x + threadIdx.x;
    int stride = gridDim.x * blockDim.x;
    uint2* out = reinterpret_cast<uint2*>(g_W16);
    for (int i = idx; i < n4; i += stride) {
        float4 v = w[i];
        float a0 = (fabsf(v.x) >= t) ? v.x : 0.0f;
        float a1 = (fabsf(v.y) >= t) ? v.y : 0.0f;
        float a2 = (fabsf(v.z) >= t) ? v.z : 0.0f;
        float a3 = (fabsf(v.w) >= t) ? v.w : 0.0f;
        __half2 h0 = __floats2half2_rn(a0, a1);
        __half2 h1 = __floats2half2_rn(a2, a3);
        uint2 o;
        o.x = *reinterpret_cast<unsigned*>(&h0);
        o.y = *reinterpret_cast<unsigned*>(&h1);
        out[i] = o;
    }
}

// ---- GEMM: 128x128 CTA tile, 4 warps (64x64 warp tiles), 3-stage cp.async, occ=2,
// ----       register double-buffered fragments across ks (hide ldsm latency) ----
#define BM 128
#define BN 128
#define BKH 64                      // K halves per stage (128 B rows -> SW128)
#define NK (K_DIM / BKH)            // 64
#define STG 3
#define OP_BYTES (BM * 128)         // 16384
#define STAGE_B (2 * OP_BYTES)      // 32768
#define SMEM_GEMM (STG * STAGE_B)   // 98304 per CTA (x2 CTAs = 192K < 228K)
#define NTHR 128

__device__ __forceinline__ void load_stage(uint32_t st, int m0, int n0, int kidx, int tid) {
    const __half* Xp = g_X16 + (size_t)m0 * K_DIM + (size_t)kidx * BKH;
    const __half* Wp = g_W16 + (size_t)n0 * K_DIM + (size_t)kidx * BKH;
#pragma unroll
    for (int i = 0; i < 8; i++) {
        int c = tid + i * NTHR;          // 0..1023 (128 rows x 8 chunks)
        int row = c >> 3, ci = c & 7;
        cp16(st + row * 128 + ((ci ^ (row & 7)) << 4), Xp + (size_t)row * K_DIM + ci * 8);
    }
#pragma unroll
    for (int i = 0; i < 8; i++) {
        int c = tid + i * NTHR;
        int row = c >> 3, ci = c & 7;
        cp16(st + OP_BYTES + row * 128 + ((ci ^ (row & 7)) << 4), Wp + (size_t)row * K_DIM + ci * 8);
    }
}

__device__ __forceinline__ void ld_frags(uint32_t sA, uint32_t sB, int chunk,
                                         int warp_m, int warp_n, int r16,
                                         uint32_t a[4][4], uint32_t b[4][4]) {
#pragma unroll
    for (int mt = 0; mt < 4; mt++) {
        int row = warp_m * 64 + mt * 16 + r16;
        uint32_t ad = sA + row * 128 + ((chunk ^ (row & 7)) << 4);
        ldsm4(a[mt][0], a[mt][1], a[mt][2], a[mt][3], ad);
    }
#pragma unroll
    for (int bt = 0; bt < 4; bt++) {
        int row = warp_n * 64 + bt * 16 + r16;
        uint32_t ad = sB + row * 128 + ((chunk ^ (row & 7)) << 4);
        ldsm4(b[bt][0], b[bt][1], b[bt][2], b[bt][3], ad);
    }
}

__global__ void __launch_bounds__(NTHR, 2) gemm_kernel(const float* __restrict__ bias,
                                                       float* __restrict__ out) {
    extern __shared__ char smraw[];
    const uint32_t sbase = smem_u32(smraw);
    const int tid = threadIdx.x;
    const int wid = tid >> 5;
    const int lane = tid & 31;
    const int warp_m = wid >> 1;     // 0..1 (64 rows each)
    const int warp_n = wid & 1;      // 0..1 (64 cols each)
    const int m0 = blockIdx.y * BM;
    const int n0 = blockIdx.x * BN;

    float acc[4][8][4];
#pragma unroll
    for (int i = 0; i < 4; i++)
#pragma unroll
        for (int j = 0; j < 8; j++)
#pragma unroll
            for (int k = 0; k < 4; k++) acc[i][j][k] = 0.0f;

    // ldmatrix lane geometry
    const int g  = lane >> 3;             // 0..3
    const int lr = lane & 7;
    const int r16 = ((g & 1) << 3) + lr;  // row within a 16-row tile
    const int kg  = g >> 1;               // 16B chunk parity within k16

    uint32_t af[2][4][4], bf[2][4][4];

    // prologue
    load_stage(sbase + 0 * STAGE_B, m0, n0, 0, tid); cp_commit();
    load_stage(sbase + 1 * STAGE_B, m0, n0, 1, tid); cp_commit();

    for (int ki = 0; ki < NK; ki++) {
        if (ki + 2 < NK) load_stage(sbase + ((ki + 2) % STG) * STAGE_B, m0, n0, ki + 2, tid);
        cp_commit();
        cp_wait2();          // stage ki resident
        __syncthreads();

        const uint32_t sA = sbase + (uint32_t)(ki % STG) * STAGE_B;
        const uint32_t sB = sA + OP_BYTES;

        // preload ks=0 fragments
        ld_frags(sA, sB, kg, warp_m, warp_n, r16, af[0], bf[0]);

#pragma unroll
        for (int ks = 0; ks < 4; ks++) {
            int cur = ks & 1, nxt = cur ^ 1;
            if (ks < 3)   // prefetch next k16's fragments before consuming current
                ld_frags(sA, sB, (ks + 1) * 2 + kg, warp_m, warp_n, r16, af[nxt], bf[nxt]);
#pragma unroll
            for (int mt = 0; mt < 4; mt++)
#pragma unroll
                for (int nt = 0; nt < 8; nt++) {
                    int bt = nt >> 1, od = nt & 1;
                    mma16816(acc[mt][nt], af[cur][mt], bf[cur][bt][od], bf[cur][bt][2 + od]);
                }
        }
        __syncthreads();    // protect stage (ki%STG) before it is reloaded
    }

    // epilogue
    const int qr = lane >> 2, qc = lane & 3;
#pragma unroll
    for (int nt = 0; nt < 8; nt++) {
        int col = n0 + warp_n * 64 + nt * 8 + qc * 2;
        float2 bb = *reinterpret_cast<const float2*>(bias + col);
#pragma unroll
        for (int mt = 0; mt < 4; mt++) {
            int r0 = m0 + warp_m * 64 + mt * 16 + qr;
            float2 v0, v1;
            v0.x = acc[mt][nt][0] + bb.x;  v0.y = acc[mt][nt][1] + bb.y;
            v1.x = acc[mt][nt][2] + bb.x;  v1.y = acc[mt][nt][3] + bb.y;
            *reinterpret_cast<float2*>(out + (size_t)r0 * N_DIM + col) = v0;
            *reinterpret_cast<float2*>(out + (size_t)(r0 + 8) * N_DIM + col) = v1;
        }
    }
}

// ---------------- launch ----------------
extern "C" void kernel_launch(void* const* d_in, const int* in_sizes, int n_in,
                              void* d_out, int out_size) {
    (void)in_sizes; (void)n_in; (void)out_size;
    const float4* x4 = reinterpret_cast<const float4*>(d_in[0]);
    const float4* w4 = reinterpret_cast<const float4*>(d_in[1]);
    const float*  bias = reinterpret_cast<const float*>(d_in[2]);
    float* out = reinterpret_cast<float*>(d_out);

    const int NW4 = (N_DIM * K_DIM) / 4;   // 4194304
    const int NX4 = (M_DIM * K_DIM) / 4;   // 8388608

    cudaFuncSetAttribute(gemm_kernel, cudaFuncAttributeMaxDynamicSharedMemorySize, SMEM_GEMM);

    zero_kernel<<<512, 256>>>();
    hist1_kernel<<<1184, 256>>>(w4, NW4);
    scan1_kernel<<<1, 1024>>>(RANK_K);
    hist2_kernel<<<1184, 256>>>(w4, NW4);
    scan2_kernel<<<1, 1024>>>(RANK_K);
    conv_x_kernel<<<1184, 256>>>(x4, NX4);
    conv_w_kernel<<<1184, 256>>>(w4, NW4);
    gemm_kernel<<<dim3(N_DIM / BN, M_DIM / BM), NTHR, SMEM_GEMM>>>(bias, out);
}